// round 12
// baseline (speedup 1.0000x reference)
#include <cuda_runtime.h>
#include <cuda_bf16.h>
#include <cstdint>

// ---------------- problem constants ----------------
#define CLASSES   100000
#define CPAD      100096
#define KDIM      512
#define BATCHN    512
#define NCTA      782                  // class tiles of 128
#define PPAD      784
#define NCHUNK    8                    // K chunks of 64
#define EXPK      92.33248261689366f   // 64 * log2(e)

static constexpr float C_COS_M = 0.8775825618903728f;
static constexpr float C_SIN_M = 0.479425538604203f;
static constexpr float C_TH    = -0.8775825618903728f;
static constexpr float C_MM    = 0.23971276930210156f;

// ---------------- device scratch ----------------
__device__ __nv_bfloat16 g_xn[BATCHN * KDIM];
__device__ __nv_bfloat16 g_wb[(size_t)CPAD * KDIM];    // fallback path only
__device__ float g_partials[(size_t)BATCHN * PPAD];
__device__ float g_cost[BATCHN];
__device__ float g_lossb[BATCHN];
__device__ int   g_tgt[BATCHN];

// ---------------- helpers ----------------
__device__ __forceinline__ uint32_t smem_u32(const void* p) {
    uint32_t a;
    asm("{ .reg .u64 t; cvta.to.shared.u64 t, %1; cvt.u32.u64 %0, t; }" : "=r"(a) : "l"(p));
    return a;
}
__device__ __forceinline__ void cp_async16_cg(uint32_t saddr, const void* gptr) {
    asm volatile("cp.async.cg.shared.global [%0], [%1], 16;"
                 :: "r"(saddr), "l"(__cvta_generic_to_global(gptr)));
}
__device__ __forceinline__ void cp_async16_ca(uint32_t saddr, const void* gptr) {
    asm volatile("cp.async.ca.shared.global [%0], [%1], 16;"
                 :: "r"(saddr), "l"(__cvta_generic_to_global(gptr)));
}
__device__ __forceinline__ void cp_commit() {
    asm volatile("cp.async.commit_group;" ::: "memory");
}
template <int N>
__device__ __forceinline__ void cp_wait() {
    asm volatile("cp.async.wait_group %0;" :: "n"(N) : "memory");
}
__device__ __forceinline__ void ldsm_x4(uint32_t* r, uint32_t addr) {
    asm volatile("ldmatrix.sync.aligned.m8n8.x4.shared.b16 {%0,%1,%2,%3}, [%4];"
                 : "=r"(r[0]), "=r"(r[1]), "=r"(r[2]), "=r"(r[3]) : "r"(addr));
}
__device__ __forceinline__ void mma_bf16(float* d, const uint32_t* a, uint32_t b0, uint32_t b1) {
    asm volatile(
        "mma.sync.aligned.m16n8k16.row.col.f32.bf16.bf16.f32 "
        "{%0,%1,%2,%3}, {%4,%5,%6,%7}, {%8,%9}, {%0,%1,%2,%3};"
        : "+f"(d[0]), "+f"(d[1]), "+f"(d[2]), "+f"(d[3])
        : "r"(a[0]), "r"(a[1]), "r"(a[2]), "r"(a[3]), "r"(b0), "r"(b1));
}
__device__ __forceinline__ uint32_t pack_bf16x2(float a, float b) {
    __nv_bfloat162 p = __floats2bfloat162_rn(a, b);
    return *(uint32_t*)&p;
}

// ======================= K-1: dtype-robust target conversion =======================
__global__ void __launch_bounds__(512) k_prep_targets(const int* __restrict__ t32) {
    __shared__ int nz;
    int tid = threadIdx.x;
    if (tid == 0) nz = 0;
    __syncthreads();
    int v = t32[tid];
    if ((tid & 1) && v != 0) atomicAdd(&nz, 1);
    __syncthreads();
    g_tgt[tid] = (nz == 0) ? t32[2 * tid] : v;
}

// ======================= K1: normalize x -> bf16 =======================
__global__ void __launch_bounds__(128) k_norm_x(const float* __restrict__ x) {
    __shared__ float red[4];
    int b = blockIdx.x;
    int tid = threadIdx.x;
    float4 v = *(const float4*)(x + (size_t)b * KDIM + tid * 4);
    float sq = v.x * v.x + v.y * v.y + v.z * v.z + v.w * v.w;
    #pragma unroll
    for (int m = 16; m >= 1; m >>= 1) sq += __shfl_xor_sync(0xffffffffu, sq, m);
    if ((tid & 31) == 0) red[tid >> 5] = sq;
    __syncthreads();
    float inv = 1.0f / fmaxf(sqrtf(red[0] + red[1] + red[2] + red[3]), 1e-12f);
    uint2 pk;
    pk.x = pack_bf16x2(v.x * inv, v.y * inv);
    pk.y = pack_bf16x2(v.z * inv, v.w * inv);
    *(uint2*)(&g_xn[(size_t)b * KDIM + tid * 4]) = pk;
}

// ======================= FUSED GEMM: smem layout =======================
#define OFF_BR   0            // resident B bf16: 8 chunks * 16384 = 131072
#define OFF_A    131072       // A tiles: 2 groups * 2 stages * 16384 = 65536
#define OFF_F    196608       // f32 staging 32768 (reused as rsum in epilogues)
#define OFF_SS   229376       // sumsq: 4 quarters * 128 f32 = 2048
#define SMEM_FUSED 232448     // exactly opt-in max (231424 + 1024 align pad)

// 512 threads, 16 warps. Group g (8 warps) handles btile g (phase 0) and 2+g (phase 1).
__global__ void __launch_bounds__(512, 1) k_gemm_fused(const float* __restrict__ w) {
    extern __shared__ char dsm[];
    uint32_t base = smem_u32(dsm);
    uint32_t A = (base + 1023u) & ~1023u;
    char* SA = dsm + (A - base);

    int tid = threadIdx.x;
    int wid = tid >> 5;
    int lid = tid & 31;
    int g   = wid >> 3;            // group 0/1
    int gtid = tid & 255;
    int wg  = wid & 7;
    int warpM = wg >> 1;           // 0..3
    int warpN = wg & 1;            // 0..1

    int ctile = blockIdx.x;
    int cls0 = ctile * 128;

    // ---- converter mapping: thread -> (row cr, quarter cq) ----
    int cr = tid & 127;
    int cq = tid >> 7;             // 0..3
    bool okrow = (cls0 + cr) < CLASSES;
    uint32_t cxor = (uint32_t)((cr & 7) << 4);
    float* ssq = (float*)(SA + OFF_SS) + cq * 128 + cr;

    // ---- B f32 loader (coalesced): idx -> (row, 16B group j) ----
    auto ld_B32 = [&](int kc) {
        #pragma unroll
        for (int it = 0; it < 4; it++) {
            int idx = tid + it * 512;
            int r = idx >> 4;
            int j = idx & 15;
            if (cls0 + r < CLASSES)
                cp_async16_cg(A + OFF_F + (uint32_t)(r * 256 + ((j ^ (r & 7)) << 4)),
                              (const char*)w + (size_t)(cls0 + r) * 2048 + kc * 256 + j * 16);
        }
    };

    // ---- A loader (per group, 2 stages) ----
    int lrow = gtid >> 3;
    int lc8 = gtid & 7;
    uint32_t stA = A + OFF_A + (uint32_t)(g * 32768 + lrow * 128 + ((lc8 * 16) ^ ((lrow & 7) << 4)));
    auto ld_A = [&](const char* pA, int kc, int st) {
        #pragma unroll
        for (int i = 0; i < 4; i++)
            cp_async16_ca(stA + st * 16384 + i * 4096, pA + i * 32768 + kc * 128);
    };

    // ---- converter: f32 staging -> resident bf16 chunk + sumsq ----
    auto convert = [&](int kc) {
        float4 v[4];
        #pragma unroll
        for (int i = 0; i < 4; i++) {
            if (okrow)
                v[i] = *(const float4*)(SA + OFF_F + cr * 256 + (((cq * 4 + i) ^ (cr & 7)) << 4));
            else
                v[i] = make_float4(0.f, 0.f, 0.f, 0.f);
        }
        float s = 0.0f;
        #pragma unroll
        for (int i = 0; i < 4; i++)
            s += v[i].x * v[i].x + v[i].y * v[i].y + v[i].z * v[i].z + v[i].w * v[i].w;
        *ssq += s;
        uint4 ulo, uhi;
        ulo.x = pack_bf16x2(v[0].x, v[0].y); ulo.y = pack_bf16x2(v[0].z, v[0].w);
        ulo.z = pack_bf16x2(v[1].x, v[1].y); ulo.w = pack_bf16x2(v[1].z, v[1].w);
        uhi.x = pack_bf16x2(v[2].x, v[2].y); uhi.y = pack_bf16x2(v[2].z, v[2].w);
        uhi.z = pack_bf16x2(v[3].x, v[3].y); uhi.w = pack_bf16x2(v[3].z, v[3].w);
        char* res = SA + OFF_BR + kc * 16384 + cr * 128;
        *(uint4*)(res + (((uint32_t)(cq * 32)) ^ cxor)) = ulo;
        *(uint4*)(res + (((uint32_t)(cq * 32 + 16)) ^ cxor)) = uhi;
    };

    // ---- LDSM bases ----
    int lr = lid & 15;
    int lh = (lid >> 4) * 16;
    uint32_t pat = (uint32_t)((lr & 7) << 4);
    uint32_t ko[4];
    #pragma unroll
    for (int ks = 0; ks < 4; ks++) ko[ks] = (uint32_t)((ks * 32 + lh) ^ pat);
    uint32_t ldAb = A + OFF_A + (uint32_t)(g * 32768 + (warpM * 32 + lr) * 128);
    uint32_t ldBb = A + OFF_BR + (uint32_t)((warpN * 64 + lr) * 128);

    float acc[2][8][4];
    uint32_t bfr[2][4][4];
    uint32_t afr[2][2][4];

    auto zero_acc = [&]() {
        #pragma unroll
        for (int i = 0; i < 2; i++)
            #pragma unroll
            for (int j = 0; j < 8; j++)
                #pragma unroll
                for (int q = 0; q < 4; q++) acc[i][j][q] = 0.0f;
    };

    auto mma_chunk = [&](int kc) {
        uint32_t bOff = (uint32_t)(kc * 16384);
        uint32_t aOff = (uint32_t)((kc & 1) * 16384);
        #pragma unroll
        for (int nt4 = 0; nt4 < 4; nt4++)
            ldsm_x4(bfr[0][nt4], ldBb + bOff + nt4 * 2048 + ko[0]);
        #pragma unroll
        for (int mt = 0; mt < 2; mt++)
            ldsm_x4(afr[0][mt], ldAb + aOff + mt * 2048 + ko[0]);
        #pragma unroll
        for (int ks = 0; ks < 4; ks++) {
            int cur = ks & 1;
            int nxt = cur ^ 1;
            if (ks < 3) {
                #pragma unroll
                for (int nt4 = 0; nt4 < 4; nt4++)
                    ldsm_x4(bfr[nxt][nt4], ldBb + bOff + nt4 * 2048 + ko[ks + 1]);
                #pragma unroll
                for (int mt = 0; mt < 2; mt++)
                    ldsm_x4(afr[nxt][mt], ldAb + aOff + mt * 2048 + ko[ks + 1]);
            }
            #pragma unroll
            for (int mt = 0; mt < 2; mt++) {
                #pragma unroll
                for (int nt4 = 0; nt4 < 4; nt4++) {
                    mma_bf16(acc[mt][nt4 * 2 + 0], afr[cur][mt], bfr[cur][nt4][0], bfr[cur][nt4][2]);
                    mma_bf16(acc[mt][nt4 * 2 + 1], afr[cur][mt], bfr[cur][nt4][1], bfr[cur][nt4][3]);
                }
            }
        }
    };

    // ---- epilogue for one btile (per group) ----
    float* invv = (float*)(SA + OFF_SS);     // 128 f32 inverse norms (after phase 1)
    auto epilogue = [&](int b0) {
        float* rsum = (float*)(SA + OFF_F + g * 1024);
        int gg = lid >> 2;
        int tg = lid & 3;
        float invc[16];
        #pragma unroll
        for (int nt = 0; nt < 8; nt++) {
            invc[nt * 2 + 0] = invv[warpN * 64 + nt * 8 + tg * 2 + 0];
            invc[nt * 2 + 1] = invv[warpN * 64 + nt * 8 + tg * 2 + 1];
        }
        float rs[4] = {0.f, 0.f, 0.f, 0.f};
        #pragma unroll
        for (int mt = 0; mt < 2; mt++) {
            int rlo = warpM * 32 + mt * 16 + gg;
            int rhi = rlo + 8;
            int tlo = g_tgt[b0 + rlo];
            int thi = g_tgt[b0 + rhi];
            #pragma unroll
            for (int nt = 0; nt < 8; nt++) {
                int colb = warpN * 64 + nt * 8 + tg * 2;
                #pragma unroll
                for (int q = 0; q < 4; q++) {
                    int cls = cls0 + colb + (q & 1);
                    float cosv = acc[mt][nt][q] * invc[nt * 2 + (q & 1)];
                    int row = (q < 2) ? rlo : rhi;
                    int t = (q < 2) ? tlo : thi;
                    if (cls == t) {
                        g_cost[b0 + row] = cosv;
                    } else if (cls < CLASSES) {
                        rs[mt * 2 + (q >> 1)] += exp2f(fmaf(EXPK, cosv, -EXPK));
                    }
                }
            }
        }
        #pragma unroll
        for (int i = 0; i < 4; i++) {
            rs[i] += __shfl_xor_sync(0xffffffffu, rs[i], 1);
            rs[i] += __shfl_xor_sync(0xffffffffu, rs[i], 2);
        }
        if (tg == 0) {
            #pragma unroll
            for (int mt = 0; mt < 2; mt++) {
                int rlo = warpM * 32 + mt * 16 + gg;
                rsum[rlo * 2 + warpN] = rs[mt * 2 + 0];
                rsum[(rlo + 8) * 2 + warpN] = rs[mt * 2 + 1];
            }
        }
        __syncthreads();
        if (gtid < 128)
            g_partials[(size_t)(b0 + gtid) * PPAD + ctile] = rsum[gtid * 2] + rsum[gtid * 2 + 1];
    };

    // ================= prologue =================
    ((float*)(SA + OFF_SS))[tid & 511] = 0.0f;
    const char* pA0 = (const char*)g_xn + (size_t)(g * 128) * 1024 + lrow * 1024 + lc8 * 16;
    const char* pA1 = (const char*)g_xn + (size_t)((2 + g) * 128) * 1024 + lrow * 1024 + lc8 * 16;
    ld_B32(0);
    ld_A(pA0, 0, 0);
    cp_commit();
    zero_acc();
    cp_wait<0>();
    __syncthreads();

    // ================= phase 1: convert + MMA btile g =================
    #pragma unroll
    for (int kc = 0; kc < NCHUNK; kc++) {
        convert(kc);
        __syncthreads();                       // resident kc ready; staging free
        if (kc < NCHUNK - 1) {
            ld_B32(kc + 1);
            ld_A(pA0, kc + 1, (kc + 1) & 1);
        } else {
            ld_A(pA1, 0, 0);                   // prefetch phase-2 chunk 0
        }
        cp_commit();
        mma_chunk(kc);
        cp_wait<0>();
        __syncthreads();
    }

    // ---- inverse norms ----
    if (tid < 128) {
        float s = invv[tid] + invv[128 + tid] + invv[256 + tid] + invv[384 + tid];
        float iv = 1.0f / fmaxf(sqrtf(s), 1e-12f);
        __syncthreads();                       // all reads of ss done before overwrite
        invv[tid] = iv;
    } else {
        __syncthreads();
    }
    __syncthreads();

    // ---- epilogue btiles 0/1 ----
    epilogue(g * 128);
    __syncthreads();
    zero_acc();

    // ================= phase 2: MMA btile 2+g from resident B =================
    #pragma unroll
    for (int kc = 0; kc < NCHUNK; kc++) {
        if (kc < NCHUNK - 1) {
            ld_A(pA1, kc + 1, (kc + 1) & 1);
            cp_commit();
        }
        mma_chunk(kc);
        cp_wait<0>();
        __syncthreads();
    }

    // ---- epilogue btiles 2/3 ----
    epilogue((2 + g) * 128);
}

// ======================= FALLBACK path (R11): norm_w + split gemm =======================
__global__ void __launch_bounds__(128) k_norm_w(const float* __restrict__ w) {
    int row = blockIdx.x * 4 + (threadIdx.x >> 5);
    int lane = threadIdx.x & 31;
    if (row >= CLASSES) {
        #pragma unroll
        for (int i = 0; i < 4; i++)
            *(uint2*)(&g_wb[(size_t)row * KDIM + i * 128 + lane * 4]) = make_uint2(0u, 0u);
        return;
    }
    float4 v[4];
    float sq = 0.0f;
    #pragma unroll
    for (int i = 0; i < 4; i++) {
        v[i] = *(const float4*)(w + (size_t)row * KDIM + i * 128 + lane * 4);
        sq += v[i].x * v[i].x + v[i].y * v[i].y + v[i].z * v[i].z + v[i].w * v[i].w;
    }
    #pragma unroll
    for (int m = 16; m >= 1; m >>= 1) sq += __shfl_xor_sync(0xffffffffu, sq, m);
    float inv = 1.0f / fmaxf(sqrtf(sq), 1e-12f);
    #pragma unroll
    for (int i = 0; i < 4; i++) {
        uint2 pk;
        pk.x = pack_bf16x2(v[i].x * inv, v[i].y * inv);
        pk.y = pack_bf16x2(v[i].z * inv, v[i].w * inv);
        *(uint2*)(&g_wb[(size_t)row * KDIM + i * 128 + lane * 4]) = pk;
    }
}

#define SM_STAGE  32768
#define SM_RSUM   98304
#define SM_TGT    99328
#define SMEM_SPLIT (99840 + 1024)

__global__ void __launch_bounds__(256, 2) k_gemm_split() {
    extern __shared__ char dsm[];
    uint32_t base = smem_u32(dsm);
    uint32_t A = (base + 1023u) & ~1023u;
    char* SA = dsm + (A - base);

    int tid = threadIdx.x;
    int wid = tid >> 5;
    int lid = tid & 31;
    int warpM = wid >> 1;
    int warpN = wid & 1;

    int ctile = blockIdx.x >> 2;
    int btile = blockIdx.x & 3;
    int cls0 = ctile * 128;
    int b0 = btile * 128;

    int lrow = tid >> 3;
    int lcol = (tid & 7) * 16;
    uint32_t st_sw = A + (uint32_t)(lrow * 128 + (lcol ^ ((lrow & 7) << 4)));
    const char* pA = (const char*)g_xn + (size_t)b0 * 1024 + lrow * 1024 + (tid & 7) * 16;
    const char* pB = (const char*)g_wb + (size_t)cls0 * 1024 + lrow * 1024 + (tid & 7) * 16;

    auto ld = [&](int kc, int st) {
        #pragma unroll
        for (int i = 0; i < 4; i++)
            cp_async16_ca(st_sw + st * SM_STAGE + i * 4096, pA + i * 32768 + kc * 128);
        #pragma unroll
        for (int i = 0; i < 4; i++)
            cp_async16_cg(st_sw + st * SM_STAGE + 16384 + i * 4096, pB + i * 32768 + kc * 128);
        cp_commit();
    };

    int lr = lid & 15;
    int lh = (lid >> 4) * 16;
    uint32_t pat = (uint32_t)((lr & 7) << 4);
    uint32_t ko[4];
    #pragma unroll
    for (int ks = 0; ks < 4; ks++) ko[ks] = (uint32_t)((ks * 32 + lh) ^ pat);
    uint32_t ldA = A + (uint32_t)((warpM * 32 + lr) * 128);
    uint32_t ldB = A + 16384u + (uint32_t)((warpN * 64 + lr) * 128);

    float acc[2][8][4];
    #pragma unroll
    for (int i = 0; i < 2; i++)
        #pragma unroll
        for (int j = 0; j < 8; j++)
            #pragma unroll
            for (int q = 0; q < 4; q++) acc[i][j][q] = 0.0f;

    int* tgt_s = (int*)(SA + SM_TGT);
    if (tid < 128) tgt_s[tid] = g_tgt[b0 + tid];

    ld(0, 0);
    ld(1, 1);

    uint32_t bfr[2][4][4];
    uint32_t afr[2][2][4];

    #pragma unroll
    for (int kc = 0; kc < NCHUNK; kc++) {
        if (kc < NCHUNK - 1) cp_wait<1>();
        else                 cp_wait<0>();
        __syncthreads();
        if (kc + 2 < NCHUNK) ld(kc + 2, (kc + 2) % 3);
        const uint32_t sOff = (uint32_t)((kc % 3) * SM_STAGE);
        #pragma unroll
        for (int nt4 = 0; nt4 < 4; nt4++)
            ldsm_x4(bfr[0][nt4], ldB + sOff + nt4 * 2048 + ko[0]);
        #pragma unroll
        for (int mt = 0; mt < 2; mt++)
            ldsm_x4(afr[0][mt], ldA + sOff + mt * 2048 + ko[0]);
        #pragma unroll
        for (int ks = 0; ks < 4; ks++) {
            int cur = ks & 1;
            int nxt = cur ^ 1;
            if (ks < 3) {
                #pragma unroll
                for (int nt4 = 0; nt4 < 4; nt4++)
                    ldsm_x4(bfr[nxt][nt4], ldB + sOff + nt4 * 2048 + ko[ks + 1]);
                #pragma unroll
                for (int mt = 0; mt < 2; mt++)
                    ldsm_x4(afr[nxt][mt], ldA + sOff + mt * 2048 + ko[ks + 1]);
            }
            #pragma unroll
            for (int mt = 0; mt < 2; mt++) {
                #pragma unroll
                for (int nt4 = 0; nt4 < 4; nt4++) {
                    mma_bf16(acc[mt][nt4 * 2 + 0], afr[cur][mt], bfr[cur][nt4][0], bfr[cur][nt4][2]);
                    mma_bf16(acc[mt][nt4 * 2 + 1], afr[cur][mt], bfr[cur][nt4][1], bfr[cur][nt4][3]);
                }
            }
        }
        __syncthreads();
    }

    float* rsum = (float*)(SA + SM_RSUM);
    int g = lid >> 2;
    int tg = lid & 3;
    float rs[4] = {0.f, 0.f, 0.f, 0.f};
    #pragma unroll
    for (int mt = 0; mt < 2; mt++) {
        int rlo = warpM * 32 + mt * 16 + g;
        int rhi = rlo + 8;
        int tlo = tgt_s[rlo];
        int thi = tgt_s[rhi];
        #pragma unroll
        for (int nt = 0; nt < 8; nt++) {
            int colb = warpN * 64 + nt * 8 + tg * 2;
            #pragma unroll
            for (int q = 0; q < 4; q++) {
                int cls = cls0 + colb + (q & 1);
                float cosv = acc[mt][nt][q];
                int row = (q < 2) ? rlo : rhi;
                int t = (q < 2) ? tlo : thi;
                if (cls == t) {
                    g_cost[b0 + row] = cosv;
                } else if (cls < CLASSES) {
                    rs[mt * 2 + (q >> 1)] += exp2f(fmaf(EXPK, cosv, -EXPK));
                }
            }
        }
    }
    #pragma unroll
    for (int i = 0; i < 4; i++) {
        rs[i] += __shfl_xor_sync(0xffffffffu, rs[i], 1);
        rs[i] += __shfl_xor_sync(0xffffffffu, rs[i], 2);
    }
    if (tg == 0) {
        #pragma unroll
        for (int mt = 0; mt < 2; mt++) {
            int rlo = warpM * 32 + mt * 16 + g;
            rsum[rlo * 2 + warpN] = rs[mt * 2 + 0];
            rsum[(rlo + 8) * 2 + warpN] = rs[mt * 2 + 1];
        }
    }
    __syncthreads();
    if (tid < 128)
        g_partials[(size_t)(b0 + tid) * PPAD + ctile] = rsum[tid * 2] + rsum[tid * 2 + 1];
}

// ======================= K3/K4 =======================
__global__ void __launch_bounds__(256) k_reduce_b() {
    int wid = threadIdx.x >> 5;
    int lane = threadIdx.x & 31;
    int b = blockIdx.x * 8 + wid;
    float acc = 0.0f;
    for (int i = lane; i < NCTA; i += 32)
        acc += g_partials[(size_t)b * PPAD + i];
    #pragma unroll
    for (int m = 16; m >= 1; m >>= 1) acc += __shfl_xor_sync(0xffffffffu, acc, m);
    if (lane == 0) {
        float ct = g_cost[b];
        float st = sqrtf(fmaxf(1.0f - ct * ct, 0.0f));
        float phi = ct * C_COS_M - st * C_SIN_M;
        phi = (ct > C_TH) ? phi : (ct - C_MM);
        acc += exp2f(EXPK * (phi - 1.0f));
        g_lossb[b] = 64.0f + logf(acc) - 64.0f * phi;
    }
}

__global__ void __launch_bounds__(512) k_finalize(float* __restrict__ out) {
    __shared__ float red[16];
    int tid = threadIdx.x;
    float v = g_lossb[tid];
    #pragma unroll
    for (int m = 16; m >= 1; m >>= 1) v += __shfl_xor_sync(0xffffffffu, v, m);
    if ((tid & 31) == 0) red[tid >> 5] = v;
    __syncthreads();
    if (tid < 16) {
        float s = red[tid];
        #pragma unroll
        for (int m = 8; m >= 1; m >>= 1) s += __shfl_xor_sync(0xffffu, s, m);
        if (tid == 0) out[0] = s * (1.0f / (float)BATCHN);
    }
}

// ======================= launch =======================
extern "C" void kernel_launch(void* const* d_in, const int* in_sizes, int n_in,
                              void* d_out, int out_size) {
    const float* x = (const float*)d_in[0];
    const float* w = (const float*)d_in[1];
    const int* tgt_raw = (const int*)d_in[2];
    float* out = (float*)d_out;

    k_prep_targets<<<1, 512>>>(tgt_raw);
    k_norm_x<<<BATCHN, 128>>>(x);

    cudaError_t e = cudaFuncSetAttribute(
        k_gemm_fused, cudaFuncAttributeMaxDynamicSharedMemorySize, SMEM_FUSED);
    if (e == cudaSuccess) {
        k_gemm_fused<<<NCTA, 512, SMEM_FUSED>>>(w);
    } else {
        cudaGetLastError();  // clear
        cudaFuncSetAttribute(k_gemm_split, cudaFuncAttributeMaxDynamicSharedMemorySize, SMEM_SPLIT);
        k_norm_w<<<CPAD / 4, 128>>>(w);
        k_gemm_split<<<NCTA * 4, 256, SMEM_SPLIT>>>();
    }

    k_reduce_b<<<64, 256>>>();
    k_finalize<<<1, 512>>>(out);
}

// round 13
// speedup vs baseline: 1.3406x; 1.3406x over previous
#include <cuda_runtime.h>
#include <cuda_bf16.h>
#include <cstdint>

// ---------------- problem constants ----------------
#define CLASSES   100000
#define CPAD      100096               // 782*128 padded classes
#define KDIM      512
#define BATCHN    512
#define NCTA      782                  // class tiles of 128
#define PPAD      784                  // padded partial stride per batch row
#define NCHUNK    8                    // K chunks of 64
#define EXPK      92.33248261689366f   // 64 * log2(e)

static constexpr float C_COS_M = 0.8775825618903728f;   // cos(0.5)
static constexpr float C_SIN_M = 0.479425538604203f;    // sin(0.5)
static constexpr float C_TH    = -0.8775825618903728f;  // cos(pi-0.5)
static constexpr float C_MM    = 0.23971276930210156f;  // sin(pi-0.5)*0.5

// ---------------- device scratch (static: no allocations allowed) ----------------
__device__ __nv_bfloat16 g_xn[BATCHN * KDIM];          // normalized x, bf16
__device__ __nv_bfloat16 g_wb[(size_t)CPAD * KDIM];    // normalized w, bf16 (zero-padded)
__device__ float g_partials[(size_t)BATCHN * PPAD];    // per (b, class-tile) exp sums
__device__ float g_cost[BATCHN];                       // cosine at target class
__device__ float g_lossb[BATCHN];                      // per-sample loss
__device__ int   g_tgt[BATCHN];                        // targets as int32 (dtype-robust)

// ---------------- helpers ----------------
__device__ __forceinline__ uint32_t smem_u32(const void* p) {
    uint32_t a;
    asm("{ .reg .u64 t; cvta.to.shared.u64 t, %1; cvt.u32.u64 %0, t; }" : "=r"(a) : "l"(p));
    return a;
}
__device__ __forceinline__ void cp_async16_cg(uint32_t saddr, const void* gptr) {
    asm volatile("cp.async.cg.shared.global [%0], [%1], 16;"
                 :: "r"(saddr), "l"(__cvta_generic_to_global(gptr)));
}
__device__ __forceinline__ void cp_async16_ca(uint32_t saddr, const void* gptr) {
    asm volatile("cp.async.ca.shared.global [%0], [%1], 16;"
                 :: "r"(saddr), "l"(__cvta_generic_to_global(gptr)));
}
__device__ __forceinline__ void cp_commit() {
    asm volatile("cp.async.commit_group;" ::: "memory");
}
template <int N>
__device__ __forceinline__ void cp_wait() {
    asm volatile("cp.async.wait_group %0;" :: "n"(N) : "memory");
}
__device__ __forceinline__ void ldsm_x4(uint32_t* r, uint32_t addr) {
    asm volatile("ldmatrix.sync.aligned.m8n8.x4.shared.b16 {%0,%1,%2,%3}, [%4];"
                 : "=r"(r[0]), "=r"(r[1]), "=r"(r[2]), "=r"(r[3]) : "r"(addr));
}
__device__ __forceinline__ void mma_bf16(float* d, const uint32_t* a, uint32_t b0, uint32_t b1) {
    asm volatile(
        "mma.sync.aligned.m16n8k16.row.col.f32.bf16.bf16.f32 "
        "{%0,%1,%2,%3}, {%4,%5,%6,%7}, {%8,%9}, {%0,%1,%2,%3};"
        : "+f"(d[0]), "+f"(d[1]), "+f"(d[2]), "+f"(d[3])
        : "r"(a[0]), "r"(a[1]), "r"(a[2]), "r"(a[3]), "r"(b0), "r"(b1));
}
__device__ __forceinline__ uint32_t pack_bf16x2(float a, float b) {
    __nv_bfloat162 p = __floats2bfloat162_rn(a, b);
    return *(uint32_t*)&p;
}

// ---------------- dynamic smem layout for GEMM (3-stage) ----------------
#define SM_STAGE  32768
#define SM_RSUM   98304     // 128*2 f32 = 1024
#define SM_TGT    99328     // 128 int = 512
#define SMEM_DYN  (99840 + 1024)

// ======================= K0: normalize weights -> bf16 (warp per row) =======================
__global__ void __launch_bounds__(128) k_norm_w(const float* __restrict__ w) {
    int row = blockIdx.x * 4 + (threadIdx.x >> 5);   // one warp per row
    int lane = threadIdx.x & 31;
    if (row >= CLASSES) {
        #pragma unroll
        for (int i = 0; i < 4; i++)
            *(uint2*)(&g_wb[(size_t)row * KDIM + i * 128 + lane * 4]) = make_uint2(0u, 0u);
        return;
    }
    float4 v[4];
    float sq = 0.0f;
    #pragma unroll
    for (int i = 0; i < 4; i++) {
        v[i] = *(const float4*)(w + (size_t)row * KDIM + i * 128 + lane * 4);
        sq += v[i].x * v[i].x + v[i].y * v[i].y + v[i].z * v[i].z + v[i].w * v[i].w;
    }
    #pragma unroll
    for (int m = 16; m >= 1; m >>= 1) sq += __shfl_xor_sync(0xffffffffu, sq, m);
    float inv = 1.0f / fmaxf(sqrtf(sq), 1e-12f);
    #pragma unroll
    for (int i = 0; i < 4; i++) {
        uint2 pk;
        pk.x = pack_bf16x2(v[i].x * inv, v[i].y * inv);
        pk.y = pack_bf16x2(v[i].z * inv, v[i].w * inv);
        *(uint2*)(&g_wb[(size_t)row * KDIM + i * 128 + lane * 4]) = pk;
    }
}

// ======================= K1: normalize x -> bf16 (+ target prep in block 0) ============
__global__ void __launch_bounds__(128) k_norm_x(const float* __restrict__ x,
                                                const int* __restrict__ t32) {
    __shared__ float red[4];
    __shared__ int nz;
    int b = blockIdx.x;
    int tid = threadIdx.x;

    // ---- target prep (block 0 only): dtype-robust int64/int32 detection ----
    int tv[4];
    if (b == 0) {
        if (tid == 0) nz = 0;
        #pragma unroll
        for (int i = 0; i < 4; i++) tv[i] = t32[tid + i * 128];
    }

    float4 v = *(const float4*)(x + (size_t)b * KDIM + tid * 4);
    float sq = v.x * v.x + v.y * v.y + v.z * v.z + v.w * v.w;
    #pragma unroll
    for (int m = 16; m >= 1; m >>= 1) sq += __shfl_xor_sync(0xffffffffu, sq, m);
    if ((tid & 31) == 0) red[tid >> 5] = sq;
    __syncthreads();

    if (b == 0) {
        #pragma unroll
        for (int i = 0; i < 4; i++) {
            int idx = tid + i * 128;
            if ((idx & 1) && tv[i] != 0) atomicAdd(&nz, 1);
        }
    }
    __syncthreads();

    float inv = 1.0f / fmaxf(sqrtf(red[0] + red[1] + red[2] + red[3]), 1e-12f);
    uint2 pk;
    pk.x = pack_bf16x2(v.x * inv, v.y * inv);
    pk.y = pack_bf16x2(v.z * inv, v.w * inv);
    *(uint2*)(&g_xn[(size_t)b * KDIM + tid * 4]) = pk;

    if (b == 0) {
        bool is64 = (nz == 0);
        #pragma unroll
        for (int i = 0; i < 4; i++) {
            int idx = tid + i * 128;
            g_tgt[idx] = is64 ? t32[2 * idx] : t32[idx];
        }
    }
}

// ======================= K2: HMMA GEMM + partial LSE =======================
// 256 threads, 8 warps 4x2, warp tile 32x64, 3-stage cp.async, unrolled kc,
// decomposed swizzle, same-chunk fragment prefetch, ONE barrier per chunk.
__global__ void __launch_bounds__(256, 2) k_gemm() {
    extern __shared__ char dsm[];
    uint32_t base = smem_u32(dsm);
    uint32_t A = (base + 1023u) & ~1023u;
    char* SA = dsm + (A - base);

    int tid = threadIdx.x;
    int wid = tid >> 5;
    int lid = tid & 31;
    int warpM = wid >> 1;          // 0..3  (32 batch rows each)
    int warpN = wid & 1;           // 0..1  (64 class cols each)

    int ctile = blockIdx.x >> 2;
    int btile = blockIdx.x & 3;
    int cls0 = ctile * 128;
    int b0 = btile * 128;

    // swz(r*128 + c) = r*128 + (c ^ ((r&7)<<4))  for c < 128
    int lrow = tid >> 3;                   // 0..31
    int lcol = (tid & 7) * 16;
    uint32_t st_sw = A + (uint32_t)(lrow * 128 + (lcol ^ ((lrow & 7) << 4)));
    const char* pA = (const char*)g_xn + (size_t)b0 * 1024 + lrow * 1024 + (tid & 7) * 16;
    const char* pB = (const char*)g_wb + (size_t)cls0 * 1024 + lrow * 1024 + (tid & 7) * 16;

    auto ld = [&](int kc, int st) {
        #pragma unroll
        for (int i = 0; i < 4; i++)
            cp_async16_ca(st_sw + st * SM_STAGE + i * 4096, pA + i * 32768 + kc * 128);
        #pragma unroll
        for (int i = 0; i < 4; i++)
            cp_async16_cg(st_sw + st * SM_STAGE + 16384 + i * 4096, pB + i * 32768 + kc * 128);
        cp_commit();
    };

    int lr = lid & 15;
    int lh = (lid >> 4) * 16;
    uint32_t pat = (uint32_t)((lr & 7) << 4);
    uint32_t ko[4];
    #pragma unroll
    for (int ks = 0; ks < 4; ks++) ko[ks] = (uint32_t)((ks * 32 + lh) ^ pat);
    uint32_t ldA = A + (uint32_t)((warpM * 32 + lr) * 128);
    uint32_t ldB = A + 16384u + (uint32_t)((warpN * 64 + lr) * 128);

    float acc[2][8][4];
    #pragma unroll
    for (int i = 0; i < 2; i++)
        #pragma unroll
        for (int j = 0; j < 8; j++)
            #pragma unroll
            for (int q = 0; q < 4; q++) acc[i][j][q] = 0.0f;

    int* tgt_s = (int*)(SA + SM_TGT);
    if (tid < 128) tgt_s[tid] = g_tgt[b0 + tid];

    ld(0, 0);
    ld(1, 1);

    uint32_t bfr[2][4][4];
    uint32_t afr[2][2][4];

    #pragma unroll
    for (int kc = 0; kc < NCHUNK; kc++) {
        if (kc < NCHUNK - 1) cp_wait<1>();
        else                 cp_wait<0>();
        __syncthreads();      // single barrier: stage kc visible; stage (kc+2)%3 reusable

        if (kc + 2 < NCHUNK) ld(kc + 2, (kc + 2) % 3);

        const uint32_t sOff = (uint32_t)((kc % 3) * SM_STAGE);

        #pragma unroll
        for (int nt4 = 0; nt4 < 4; nt4++)
            ldsm_x4(bfr[0][nt4], ldB + sOff + nt4 * 2048 + ko[0]);
        #pragma unroll
        for (int mt = 0; mt < 2; mt++)
            ldsm_x4(afr[0][mt], ldA + sOff + mt * 2048 + ko[0]);

        #pragma unroll
        for (int ks = 0; ks < 4; ks++) {
            int cur = ks & 1;
            int nxt = cur ^ 1;
            if (ks < 3) {
                #pragma unroll
                for (int nt4 = 0; nt4 < 4; nt4++)
                    ldsm_x4(bfr[nxt][nt4], ldB + sOff + nt4 * 2048 + ko[ks + 1]);
                #pragma unroll
                for (int mt = 0; mt < 2; mt++)
                    ldsm_x4(afr[nxt][mt], ldA + sOff + mt * 2048 + ko[ks + 1]);
            }
            #pragma unroll
            for (int mt = 0; mt < 2; mt++) {
                #pragma unroll
                for (int nt4 = 0; nt4 < 4; nt4++) {
                    mma_bf16(acc[mt][nt4 * 2 + 0], afr[cur][mt], bfr[cur][nt4][0], bfr[cur][nt4][2]);
                    mma_bf16(acc[mt][nt4 * 2 + 1], afr[cur][mt], bfr[cur][nt4][1], bfr[cur][nt4][3]);
                }
            }
        }
        // no trailing barrier: next iteration's top barrier orders stage reuse
    }

    // ---------------- epilogue: deterministic partial LSE ----------------
    float* rsum = (float*)(SA + SM_RSUM);
    int g = lid >> 2;
    int tg = lid & 3;

    float rs[4] = {0.f, 0.f, 0.f, 0.f};
    #pragma unroll
    for (int mt = 0; mt < 2; mt++) {
        int rlo = warpM * 32 + mt * 16 + g;
        int rhi = rlo + 8;
        int tlo = tgt_s[rlo];
        int thi = tgt_s[rhi];
        #pragma unroll
        for (int nt = 0; nt < 8; nt++) {
            int colb = warpN * 64 + nt * 8 + tg * 2;
            #pragma unroll
            for (int q = 0; q < 4; q++) {
                int cls = cls0 + colb + (q & 1);
                float cosv = acc[mt][nt][q];
                int row = (q < 2) ? rlo : rhi;
                int t = (q < 2) ? tlo : thi;
                if (cls == t) {
                    g_cost[b0 + row] = cosv;
                } else if (cls < CLASSES) {
                    rs[mt * 2 + (q >> 1)] += exp2f(fmaf(EXPK, cosv, -EXPK));
                }
            }
        }
    }
    #pragma unroll
    for (int i = 0; i < 4; i++) {
        rs[i] += __shfl_xor_sync(0xffffffffu, rs[i], 1);
        rs[i] += __shfl_xor_sync(0xffffffffu, rs[i], 2);
    }
    if (tg == 0) {
        #pragma unroll
        for (int mt = 0; mt < 2; mt++) {
            int rlo = warpM * 32 + mt * 16 + g;
            rsum[rlo * 2 + warpN] = rs[mt * 2 + 0];
            rsum[(rlo + 8) * 2 + warpN] = rs[mt * 2 + 1];
        }
    }
    __syncthreads();
    if (tid < 128) {
        g_partials[(size_t)(b0 + tid) * PPAD + ctile] = rsum[tid * 2] + rsum[tid * 2 + 1];
    }
}

// ======================= K3: per-batch reduce + margin (4 warps per row) ==============
__global__ void __launch_bounds__(256) k_reduce_b() {
    __shared__ float red[2][4];
    int tid = threadIdx.x;
    int half = tid >> 7;               // row within block (0/1)
    int b = blockIdx.x * 2 + half;
    int wrow = (tid >> 5) & 3;         // warp within row (0..3)
    int lane = tid & 31;

    float acc = 0.0f;
    for (int i = wrow * 32 + lane; i < NCTA; i += 128)
        acc += g_partials[(size_t)b * PPAD + i];
    #pragma unroll
    for (int m = 16; m >= 1; m >>= 1) acc += __shfl_xor_sync(0xffffffffu, acc, m);
    if (lane == 0) red[half][wrow] = acc;
    __syncthreads();
    if ((tid & 127) == 0) {
        float S = red[half][0] + red[half][1] + red[half][2] + red[half][3];
        float ct = g_cost[b];
        float st = sqrtf(fmaxf(1.0f - ct * ct, 0.0f));
        float phi = ct * C_COS_M - st * C_SIN_M;
        phi = (ct > C_TH) ? phi : (ct - C_MM);
        S += exp2f(EXPK * (phi - 1.0f));
        g_lossb[b] = 64.0f + logf(S) - 64.0f * phi;
    }
}

// ======================= K4: mean over batch =======================
__global__ void __launch_bounds__(512) k_finalize(float* __restrict__ out) {
    __shared__ float red[16];
    int tid = threadIdx.x;
    float v = g_lossb[tid];
    #pragma unroll
    for (int m = 16; m >= 1; m >>= 1) v += __shfl_xor_sync(0xffffffffu, v, m);
    if ((tid & 31) == 0) red[tid >> 5] = v;
    __syncthreads();
    if (tid < 16) {
        float s = red[tid];
        #pragma unroll
        for (int m = 8; m >= 1; m >>= 1) s += __shfl_xor_sync(0xffffu, s, m);
        if (tid == 0) out[0] = s * (1.0f / (float)BATCHN);
    }
}

// ======================= launch =======================
extern "C" void kernel_launch(void* const* d_in, const int* in_sizes, int n_in,
                              void* d_out, int out_size) {
    const float* x = (const float*)d_in[0];
    const float* w = (const float*)d_in[1];
    const int* tgt_raw = (const int*)d_in[2];
    float* out = (float*)d_out;

    cudaFuncSetAttribute(k_gemm, cudaFuncAttributeMaxDynamicSharedMemorySize, SMEM_DYN);

    k_norm_w<<<CPAD / 4, 128>>>(w);
    k_norm_x<<<BATCHN, 128>>>(x, tgt_raw);
    k_gemm<<<NCTA * 4, 256, SMEM_DYN>>>();
    k_reduce_b<<<256, 256>>>();
    k_finalize<<<1, 512>>>(out);
}

// round 14
// speedup vs baseline: 1.3566x; 1.0119x over previous
#include <cuda_runtime.h>
#include <cuda_bf16.h>
#include <cstdint>

// ---------------- problem constants ----------------
#define CLASSES   100000
#define CPAD      100096               // 782*128 padded classes
#define KDIM      512
#define BATCHN    512
#define NCTA      782                  // class tiles of 128
#define PPAD      784                  // padded partial stride per batch row
#define NCHUNK    8                    // K chunks of 64
#define EXPK      92.33248261689366f   // 64 * log2(e)

static constexpr float C_COS_M = 0.8775825618903728f;   // cos(0.5)
static constexpr float C_SIN_M = 0.479425538604203f;    // sin(0.5)
static constexpr float C_TH    = -0.8775825618903728f;  // cos(pi-0.5)
static constexpr float C_MM    = 0.23971276930210156f;  // sin(pi-0.5)*0.5

// ---------------- device scratch (static: no allocations allowed) ----------------
__device__ __nv_bfloat16 g_xn[BATCHN * KDIM];          // normalized x, bf16
__device__ __nv_bfloat16 g_wb[(size_t)CPAD * KDIM];    // normalized w, bf16 (zero-padded)
__device__ float g_partials[(size_t)BATCHN * PPAD];    // per (b, class-tile) exp sums
__device__ float g_cost[BATCHN];                       // cosine at target class
__device__ float g_lossb[BATCHN];                      // per-sample loss
__device__ int   g_tgt[BATCHN];                        // targets as int32 (dtype-robust)
__device__ unsigned g_ctr;                             // last-block-done counter

// ---------------- helpers ----------------
__device__ __forceinline__ uint32_t smem_u32(const void* p) {
    uint32_t a;
    asm("{ .reg .u64 t; cvta.to.shared.u64 t, %1; cvt.u32.u64 %0, t; }" : "=r"(a) : "l"(p));
    return a;
}
__device__ __forceinline__ void cp_async16_cg(uint32_t saddr, const void* gptr) {
    asm volatile("cp.async.cg.shared.global [%0], [%1], 16;"
                 :: "r"(saddr), "l"(__cvta_generic_to_global(gptr)));
}
__device__ __forceinline__ void cp_async16_ca(uint32_t saddr, const void* gptr) {
    asm volatile("cp.async.ca.shared.global [%0], [%1], 16;"
                 :: "r"(saddr), "l"(__cvta_generic_to_global(gptr)));
}
__device__ __forceinline__ void cp_commit() {
    asm volatile("cp.async.commit_group;" ::: "memory");
}
template <int N>
__device__ __forceinline__ void cp_wait() {
    asm volatile("cp.async.wait_group %0;" :: "n"(N) : "memory");
}
__device__ __forceinline__ void ldsm_x4(uint32_t* r, uint32_t addr) {
    asm volatile("ldmatrix.sync.aligned.m8n8.x4.shared.b16 {%0,%1,%2,%3}, [%4];"
                 : "=r"(r[0]), "=r"(r[1]), "=r"(r[2]), "=r"(r[3]) : "r"(addr));
}
__device__ __forceinline__ void mma_bf16(float* d, const uint32_t* a, uint32_t b0, uint32_t b1) {
    asm volatile(
        "mma.sync.aligned.m16n8k16.row.col.f32.bf16.bf16.f32 "
        "{%0,%1,%2,%3}, {%4,%5,%6,%7}, {%8,%9}, {%0,%1,%2,%3};"
        : "+f"(d[0]), "+f"(d[1]), "+f"(d[2]), "+f"(d[3])
        : "r"(a[0]), "r"(a[1]), "r"(a[2]), "r"(a[3]), "r"(b0), "r"(b1));
}
__device__ __forceinline__ uint32_t pack_bf16x2(float a, float b) {
    __nv_bfloat162 p = __floats2bfloat162_rn(a, b);
    return *(uint32_t*)&p;
}
__device__ __forceinline__ float ex2_approx(float x) {   // bare MUFU.EX2
    float r;
    asm("ex2.approx.f32 %0, %1;" : "=f"(r) : "f"(x));
    return r;
}

// ---------------- dynamic smem layout for GEMM (3-stage) ----------------
#define SM_STAGE  32768
#define SM_RSUM   98304     // 128*2 f32 = 1024
#define SM_TGT    99328     // 128 int = 512
#define SMEM_DYN  (99840 + 1024)

// ======================= K0: normalize weights -> bf16 (warp per row) =======================
__global__ void __launch_bounds__(128) k_norm_w(const float* __restrict__ w) {
    int row = blockIdx.x * 4 + (threadIdx.x >> 5);   // one warp per row
    int lane = threadIdx.x & 31;
    if (row >= CLASSES) {
        #pragma unroll
        for (int i = 0; i < 4; i++)
            *(uint2*)(&g_wb[(size_t)row * KDIM + i * 128 + lane * 4]) = make_uint2(0u, 0u);
        return;
    }
    float4 v[4];
    float sq = 0.0f;
    #pragma unroll
    for (int i = 0; i < 4; i++) {
        v[i] = *(const float4*)(w + (size_t)row * KDIM + i * 128 + lane * 4);
        sq += v[i].x * v[i].x + v[i].y * v[i].y + v[i].z * v[i].z + v[i].w * v[i].w;
    }
    #pragma unroll
    for (int m = 16; m >= 1; m >>= 1) sq += __shfl_xor_sync(0xffffffffu, sq, m);
    float inv = 1.0f / fmaxf(sqrtf(sq), 1e-12f);
    #pragma unroll
    for (int i = 0; i < 4; i++) {
        uint2 pk;
        pk.x = pack_bf16x2(v[i].x * inv, v[i].y * inv);
        pk.y = pack_bf16x2(v[i].z * inv, v[i].w * inv);
        *(uint2*)(&g_wb[(size_t)row * KDIM + i * 128 + lane * 4]) = pk;
    }
}

// ======================= K1: normalize x -> bf16 (+ target prep + ctr reset, block 0) ===
__global__ void __launch_bounds__(128) k_norm_x(const float* __restrict__ x,
                                                const int* __restrict__ t32) {
    __shared__ float red[4];
    __shared__ int nz;
    int b = blockIdx.x;
    int tid = threadIdx.x;

    int tv[4];
    if (b == 0) {
        if (tid == 0) { nz = 0; g_ctr = 0u; }
        #pragma unroll
        for (int i = 0; i < 4; i++) tv[i] = t32[tid + i * 128];
    }

    float4 v = *(const float4*)(x + (size_t)b * KDIM + tid * 4);
    float sq = v.x * v.x + v.y * v.y + v.z * v.z + v.w * v.w;
    #pragma unroll
    for (int m = 16; m >= 1; m >>= 1) sq += __shfl_xor_sync(0xffffffffu, sq, m);
    if ((tid & 31) == 0) red[tid >> 5] = sq;
    __syncthreads();

    if (b == 0) {
        #pragma unroll
        for (int i = 0; i < 4; i++) {
            int idx = tid + i * 128;
            if ((idx & 1) && tv[i] != 0) atomicAdd(&nz, 1);
        }
    }
    __syncthreads();

    float inv = 1.0f / fmaxf(sqrtf(red[0] + red[1] + red[2] + red[3]), 1e-12f);
    uint2 pk;
    pk.x = pack_bf16x2(v.x * inv, v.y * inv);
    pk.y = pack_bf16x2(v.z * inv, v.w * inv);
    *(uint2*)(&g_xn[(size_t)b * KDIM + tid * 4]) = pk;

    if (b == 0) {
        bool is64 = (nz == 0);
        #pragma unroll
        for (int i = 0; i < 4; i++) {
            int idx = tid + i * 128;
            g_tgt[idx] = is64 ? t32[2 * idx] : t32[idx];
        }
    }
}

// ======================= K2: HMMA GEMM + partial LSE =======================
// 256 threads, 8 warps 4x2, warp tile 32x64, 3-stage cp.async, unrolled kc,
// decomposed swizzle, same-chunk fragment prefetch, ONE barrier per chunk.
__global__ void __launch_bounds__(256, 2) k_gemm() {
    extern __shared__ char dsm[];
    uint32_t base = smem_u32(dsm);
    uint32_t A = (base + 1023u) & ~1023u;
    char* SA = dsm + (A - base);

    int tid = threadIdx.x;
    int wid = tid >> 5;
    int lid = tid & 31;
    int warpM = wid >> 1;          // 0..3  (32 batch rows each)
    int warpN = wid & 1;           // 0..1  (64 class cols each)

    int ctile = blockIdx.x >> 2;
    int btile = blockIdx.x & 3;
    int cls0 = ctile * 128;
    int b0 = btile * 128;

    // swz(r*128 + c) = r*128 + (c ^ ((r&7)<<4))  for c < 128
    int lrow = tid >> 3;                   // 0..31
    int lcol = (tid & 7) * 16;
    uint32_t st_sw = A + (uint32_t)(lrow * 128 + (lcol ^ ((lrow & 7) << 4)));
    const char* pA = (const char*)g_xn + (size_t)b0 * 1024 + lrow * 1024 + (tid & 7) * 16;
    const char* pB = (const char*)g_wb + (size_t)cls0 * 1024 + lrow * 1024 + (tid & 7) * 16;

    auto ld = [&](int kc, int st) {
        #pragma unroll
        for (int i = 0; i < 4; i++)
            cp_async16_ca(st_sw + st * SM_STAGE + i * 4096, pA + i * 32768 + kc * 128);
        #pragma unroll
        for (int i = 0; i < 4; i++)
            cp_async16_cg(st_sw + st * SM_STAGE + 16384 + i * 4096, pB + i * 32768 + kc * 128);
        cp_commit();
    };

    int lr = lid & 15;
    int lh = (lid >> 4) * 16;
    uint32_t pat = (uint32_t)((lr & 7) << 4);
    uint32_t ko[4];
    #pragma unroll
    for (int ks = 0; ks < 4; ks++) ko[ks] = (uint32_t)((ks * 32 + lh) ^ pat);
    uint32_t ldA = A + (uint32_t)((warpM * 32 + lr) * 128);
    uint32_t ldB = A + 16384u + (uint32_t)((warpN * 64 + lr) * 128);

    float acc[2][8][4];
    #pragma unroll
    for (int i = 0; i < 2; i++)
        #pragma unroll
        for (int j = 0; j < 8; j++)
            #pragma unroll
            for (int q = 0; q < 4; q++) acc[i][j][q] = 0.0f;

    int* tgt_s = (int*)(SA + SM_TGT);
    if (tid < 128) tgt_s[tid] = g_tgt[b0 + tid];

    ld(0, 0);
    ld(1, 1);

    uint32_t bfr[2][4][4];
    uint32_t afr[2][2][4];

    #pragma unroll
    for (int kc = 0; kc < NCHUNK; kc++) {
        if (kc < NCHUNK - 1) cp_wait<1>();
        else                 cp_wait<0>();
        __syncthreads();      // stage kc visible; stage (kc+2)%3 reusable

        if (kc + 2 < NCHUNK) ld(kc + 2, (kc + 2) % 3);

        const uint32_t sOff = (uint32_t)((kc % 3) * SM_STAGE);

        #pragma unroll
        for (int nt4 = 0; nt4 < 4; nt4++)
            ldsm_x4(bfr[0][nt4], ldB + sOff + nt4 * 2048 + ko[0]);
        #pragma unroll
        for (int mt = 0; mt < 2; mt++)
            ldsm_x4(afr[0][mt], ldA + sOff + mt * 2048 + ko[0]);

        #pragma unroll
        for (int ks = 0; ks < 4; ks++) {
            int cur = ks & 1;
            int nxt = cur ^ 1;
            if (ks < 3) {
                #pragma unroll
                for (int nt4 = 0; nt4 < 4; nt4++)
                    ldsm_x4(bfr[nxt][nt4], ldB + sOff + nt4 * 2048 + ko[ks + 1]);
                #pragma unroll
                for (int mt = 0; mt < 2; mt++)
                    ldsm_x4(afr[nxt][mt], ldA + sOff + mt * 2048 + ko[ks + 1]);
            }
            #pragma unroll
            for (int mt = 0; mt < 2; mt++) {
                #pragma unroll
                for (int nt4 = 0; nt4 < 4; nt4++) {
                    mma_bf16(acc[mt][nt4 * 2 + 0], afr[cur][mt], bfr[cur][nt4][0], bfr[cur][nt4][2]);
                    mma_bf16(acc[mt][nt4 * 2 + 1], afr[cur][mt], bfr[cur][nt4][1], bfr[cur][nt4][3]);
                }
            }
        }
    }

    // ---------------- epilogue: deterministic partial LSE ----------------
    float* rsum = (float*)(SA + SM_RSUM);
    int g = lid >> 2;
    int tg = lid & 3;

    float rs[4] = {0.f, 0.f, 0.f, 0.f};
    #pragma unroll
    for (int mt = 0; mt < 2; mt++) {
        int rlo = warpM * 32 + mt * 16 + g;
        int rhi = rlo + 8;
        int tlo = tgt_s[rlo];
        int thi = tgt_s[rhi];
        #pragma unroll
        for (int nt = 0; nt < 8; nt++) {
            int colb = warpN * 64 + nt * 8 + tg * 2;
            #pragma unroll
            for (int q = 0; q < 4; q++) {
                int cls = cls0 + colb + (q & 1);
                float cosv = acc[mt][nt][q];
                int row = (q < 2) ? rlo : rhi;
                int t = (q < 2) ? tlo : thi;
                if (cls == t) {
                    g_cost[b0 + row] = cosv;
                } else if (cls < CLASSES) {
                    rs[mt * 2 + (q >> 1)] += ex2_approx(fmaf(EXPK, cosv, -EXPK));
                }
            }
        }
    }
    #pragma unroll
    for (int i = 0; i < 4; i++) {
        rs[i] += __shfl_xor_sync(0xffffffffu, rs[i], 1);
        rs[i] += __shfl_xor_sync(0xffffffffu, rs[i], 2);
    }
    if (tg == 0) {
        #pragma unroll
        for (int mt = 0; mt < 2; mt++) {
            int rlo = warpM * 32 + mt * 16 + g;
            rsum[rlo * 2 + warpN] = rs[mt * 2 + 0];
            rsum[(rlo + 8) * 2 + warpN] = rs[mt * 2 + 1];
        }
    }
    __syncthreads();
    if (tid < 128) {
        g_partials[(size_t)(b0 + tid) * PPAD + ctile] = rsum[tid * 2] + rsum[tid * 2 + 1];
    }
}

// ======================= K3: reduce + margin + final mean (fused) =======================
// 64 blocks x 8 warps, warp per batch row (measured-best shape); the last block
// to finish additionally computes the final mean (deterministic fixed-order sum).
__global__ void __launch_bounds__(256) k_reduce_b(float* __restrict__ out) {
    __shared__ unsigned last;
    int tid = threadIdx.x;
    int wid = tid >> 5;
    int lane = tid & 31;
    int b = blockIdx.x * 8 + wid;

    float acc = 0.0f;
    for (int i = lane; i < NCTA; i += 32)
        acc += g_partials[(size_t)b * PPAD + i];
    #pragma unroll
    for (int m = 16; m >= 1; m >>= 1) acc += __shfl_xor_sync(0xffffffffu, acc, m);
    if (lane == 0) {
        float ct = g_cost[b];
        float st = sqrtf(fmaxf(1.0f - ct * ct, 0.0f));
        float phi = ct * C_COS_M - st * C_SIN_M;
        phi = (ct > C_TH) ? phi : (ct - C_MM);
        acc += ex2_approx(EXPK * (phi - 1.0f));
        g_lossb[b] = 64.0f + logf(acc) - 64.0f * phi;
    }
    __threadfence();
    __syncthreads();                  // all 8 rows of this block written + fenced
    if (tid == 0) last = atomicAdd(&g_ctr, 1u);
    __syncthreads();
    if (last == 63u) {                // final block: mean over 512 (fixed order)
        __shared__ float red[8];
        float v = g_lossb[tid] + g_lossb[tid + 256];
        #pragma unroll
        for (int m = 16; m >= 1; m >>= 1) v += __shfl_xor_sync(0xffffffffu, v, m);
        if (lane == 0) red[wid] = v;
        __syncthreads();
        if (tid == 0) {
            float s = 0.0f;
            #pragma unroll
            for (int i = 0; i < 8; i++) s += red[i];
            out[0] = s * (1.0f / (float)BATCHN);
        }
    }
}

// ======================= launch =======================
extern "C" void kernel_launch(void* const* d_in, const int* in_sizes, int n_in,
                              void* d_out, int out_size) {
    const float* x = (const float*)d_in[0];
    const float* w = (const float*)d_in[1];
    const int* tgt_raw = (const int*)d_in[2];
    float* out = (float*)d_out;

    cudaFuncSetAttribute(k_gemm, cudaFuncAttributeMaxDynamicSharedMemorySize, SMEM_DYN);

    k_norm_w<<<CPAD / 4, 128>>>(w);
    k_norm_x<<<BATCHN, 128>>>(x, tgt_raw);
    k_gemm<<<NCTA * 4, 256, SMEM_DYN>>>();
    k_reduce_b<<<64, 256>>>(out);
}

// round 15
// speedup vs baseline: 1.3846x; 1.0207x over previous
#include <cuda_runtime.h>
#include <cuda_bf16.h>
#include <cstdint>

// ---------------- problem constants ----------------
#define CLASSES   100000
#define CPAD      100096               // 782*128 padded classes
#define KDIM      512
#define BATCHN    512
#define NCTA      782                  // class tiles of 128
#define PPAD      784                  // padded partial stride per batch row
#define NCHUNK    8                    // K chunks of 64
#define EXPK      92.33248261689366f   // 64 * log2(e)

static constexpr float C_COS_M = 0.8775825618903728f;   // cos(0.5)
static constexpr float C_SIN_M = 0.479425538604203f;    // sin(0.5)
static constexpr float C_TH    = -0.8775825618903728f;  // cos(pi-0.5)
static constexpr float C_MM    = 0.23971276930210156f;  // sin(pi-0.5)*0.5

// ---------------- device scratch (static: no allocations allowed) ----------------
__device__ __nv_bfloat16 g_xn[BATCHN * KDIM];          // normalized x, bf16
__device__ __nv_bfloat16 g_wb[(size_t)CPAD * KDIM];    // normalized w, bf16 (zero-padded)
__device__ float g_partials[(size_t)BATCHN * PPAD];    // per (b, class-tile) exp sums
__device__ float g_cost[BATCHN];                       // cosine at target class
__device__ float g_lossb[BATCHN];                      // per-sample loss
__device__ int   g_tgt[BATCHN];                        // targets as int32 (dtype-robust)
__device__ unsigned g_ctr;                             // last-block-done counter

// ---------------- helpers ----------------
__device__ __forceinline__ uint32_t smem_u32(const void* p) {
    uint32_t a;
    asm("{ .reg .u64 t; cvta.to.shared.u64 t, %1; cvt.u32.u64 %0, t; }" : "=r"(a) : "l"(p));
    return a;
}
__device__ __forceinline__ void cp_async16_cg(uint32_t saddr, const void* gptr) {
    asm volatile("cp.async.cg.shared.global [%0], [%1], 16;"
                 :: "r"(saddr), "l"(__cvta_generic_to_global(gptr)));
}
__device__ __forceinline__ void cp_async16_ca(uint32_t saddr, const void* gptr) {
    asm volatile("cp.async.ca.shared.global [%0], [%1], 16;"
                 :: "r"(saddr), "l"(__cvta_generic_to_global(gptr)));
}
__device__ __forceinline__ void cp_commit() {
    asm volatile("cp.async.commit_group;" ::: "memory");
}
template <int N>
__device__ __forceinline__ void cp_wait() {
    asm volatile("cp.async.wait_group %0;" :: "n"(N) : "memory");
}
__device__ __forceinline__ void ldsm_x4(uint32_t* r, uint32_t addr) {
    asm volatile("ldmatrix.sync.aligned.m8n8.x4.shared.b16 {%0,%1,%2,%3}, [%4];"
                 : "=r"(r[0]), "=r"(r[1]), "=r"(r[2]), "=r"(r[3]) : "r"(addr));
}
__device__ __forceinline__ void mma_bf16(float* d, const uint32_t* a, uint32_t b0, uint32_t b1) {
    asm volatile(
        "mma.sync.aligned.m16n8k16.row.col.f32.bf16.bf16.f32 "
        "{%0,%1,%2,%3}, {%4,%5,%6,%7}, {%8,%9}, {%0,%1,%2,%3};"
        : "+f"(d[0]), "+f"(d[1]), "+f"(d[2]), "+f"(d[3])
        : "r"(a[0]), "r"(a[1]), "r"(a[2]), "r"(a[3]), "r"(b0), "r"(b1));
}
__device__ __forceinline__ uint32_t pack_bf16x2(float a, float b) {
    __nv_bfloat162 p = __floats2bfloat162_rn(a, b);
    return *(uint32_t*)&p;
}
__device__ __forceinline__ float ex2_approx(float x) {   // bare MUFU.EX2
    float r;
    asm("ex2.approx.f32 %0, %1;" : "=f"(r) : "f"(x));
    return r;
}

// ---------------- dynamic smem layout for GEMM (3-stage) ----------------
#define SM_STAGE  32768
#define SM_RSUM   98304     // 128*2 f32 = 1024
#define SM_TGT    99328     // 128 int = 512
#define SMEM_DYN  (99840 + 1024)

// ======================= K0: normalize w AND x -> bf16 (warp per row, merged) ==========
// grid = (CPAD + BATCHN)/4 blocks of 128 threads. Rows [0,CPAD) -> weights,
// rows [CPAD, CPAD+BATCHN) -> x. Block 0 additionally does target prep + ctr reset.
__global__ void __launch_bounds__(128) k_norm_all(const float* __restrict__ w,
                                                  const float* __restrict__ x,
                                                  const int* __restrict__ t32) {
    int tid = threadIdx.x;
    int row = blockIdx.x * 4 + (tid >> 5);
    int lane = tid & 31;

    // ---- target prep (block 0 only) ----
    if (blockIdx.x == 0) {
        __shared__ int nz;
        if (tid == 0) { nz = 0; g_ctr = 0u; }
        __syncthreads();
        int tv[4];
        #pragma unroll
        for (int i = 0; i < 4; i++) tv[i] = t32[tid + i * 128];
        #pragma unroll
        for (int i = 0; i < 4; i++) {
            int idx = tid + i * 128;
            if ((idx & 1) && tv[i] != 0) atomicAdd(&nz, 1);
        }
        __syncthreads();
        bool is64 = (nz == 0);
        #pragma unroll
        for (int i = 0; i < 4; i++) {
            int idx = tid + i * 128;
            g_tgt[idx] = is64 ? t32[2 * idx] : t32[idx];
        }
    }

    const float* src;
    __nv_bfloat16* dst;
    if (row < CPAD) {
        if (row >= CLASSES) {   // zero-pad tail weight rows
            #pragma unroll
            for (int i = 0; i < 4; i++)
                *(uint2*)(&g_wb[(size_t)row * KDIM + i * 128 + lane * 4]) = make_uint2(0u, 0u);
            return;
        }
        src = w + (size_t)row * KDIM;
        dst = g_wb + (size_t)row * KDIM;
    } else {
        int b = row - CPAD;     // 0..BATCHN-1
        src = x + (size_t)b * KDIM;
        dst = g_xn + (size_t)b * KDIM;
    }

    float4 v[4];
    float sq = 0.0f;
    #pragma unroll
    for (int i = 0; i < 4; i++) {
        v[i] = *(const float4*)(src + i * 128 + lane * 4);
        sq += v[i].x * v[i].x + v[i].y * v[i].y + v[i].z * v[i].z + v[i].w * v[i].w;
    }
    #pragma unroll
    for (int m = 16; m >= 1; m >>= 1) sq += __shfl_xor_sync(0xffffffffu, sq, m);
    float inv = 1.0f / fmaxf(sqrtf(sq), 1e-12f);
    #pragma unroll
    for (int i = 0; i < 4; i++) {
        uint2 pk;
        pk.x = pack_bf16x2(v[i].x * inv, v[i].y * inv);
        pk.y = pack_bf16x2(v[i].z * inv, v[i].w * inv);
        *(uint2*)(dst + i * 128 + lane * 4) = pk;
    }
}

// ======================= K2: HMMA GEMM + partial LSE =======================
// 256 threads, 8 warps 4x2, warp tile 32x64, 3-stage cp.async, unrolled kc,
// decomposed swizzle, same-chunk fragment prefetch, ONE barrier per chunk.
// Epilogue is branch-free: ALL columns summed (target term subtracted later).
__global__ void __launch_bounds__(256, 2) k_gemm() {
    extern __shared__ char dsm[];
    uint32_t base = smem_u32(dsm);
    uint32_t A = (base + 1023u) & ~1023u;
    char* SA = dsm + (A - base);

    int tid = threadIdx.x;
    int wid = tid >> 5;
    int lid = tid & 31;
    int warpM = wid >> 1;          // 0..3  (32 batch rows each)
    int warpN = wid & 1;           // 0..1  (64 class cols each)

    int ctile = blockIdx.x >> 2;
    int btile = blockIdx.x & 3;
    int cls0 = ctile * 128;
    int b0 = btile * 128;

    // swz(r*128 + c) = r*128 + (c ^ ((r&7)<<4))  for c < 128
    int lrow = tid >> 3;                   // 0..31
    int lcol = (tid & 7) * 16;
    uint32_t st_sw = A + (uint32_t)(lrow * 128 + (lcol ^ ((lrow & 7) << 4)));
    const char* pA = (const char*)g_xn + (size_t)b0 * 1024 + lrow * 1024 + (tid & 7) * 16;
    const char* pB = (const char*)g_wb + (size_t)cls0 * 1024 + lrow * 1024 + (tid & 7) * 16;

    auto ld = [&](int kc, int st) {
        #pragma unroll
        for (int i = 0; i < 4; i++)
            cp_async16_ca(st_sw + st * SM_STAGE + i * 4096, pA + i * 32768 + kc * 128);
        #pragma unroll
        for (int i = 0; i < 4; i++)
            cp_async16_cg(st_sw + st * SM_STAGE + 16384 + i * 4096, pB + i * 32768 + kc * 128);
        cp_commit();
    };

    int lr = lid & 15;
    int lh = (lid >> 4) * 16;
    uint32_t pat = (uint32_t)((lr & 7) << 4);
    uint32_t ko[4];
    #pragma unroll
    for (int ks = 0; ks < 4; ks++) ko[ks] = (uint32_t)((ks * 32 + lh) ^ pat);
    uint32_t ldA = A + (uint32_t)((warpM * 32 + lr) * 128);
    uint32_t ldB = A + 16384u + (uint32_t)((warpN * 64 + lr) * 128);

    float acc[2][8][4];
    #pragma unroll
    for (int i = 0; i < 2; i++)
        #pragma unroll
        for (int j = 0; j < 8; j++)
            #pragma unroll
            for (int q = 0; q < 4; q++) acc[i][j][q] = 0.0f;

    int* tgt_s = (int*)(SA + SM_TGT);
    if (tid < 128) tgt_s[tid] = g_tgt[b0 + tid];

    ld(0, 0);
    ld(1, 1);

    uint32_t bfr[2][4][4];
    uint32_t afr[2][2][4];

    #pragma unroll
    for (int kc = 0; kc < NCHUNK; kc++) {
        if (kc < NCHUNK - 1) cp_wait<1>();
        else                 cp_wait<0>();
        __syncthreads();      // stage kc visible; stage (kc+2)%3 reusable

        if (kc + 2 < NCHUNK) ld(kc + 2, (kc + 2) % 3);

        const uint32_t sOff = (uint32_t)((kc % 3) * SM_STAGE);

        #pragma unroll
        for (int nt4 = 0; nt4 < 4; nt4++)
            ldsm_x4(bfr[0][nt4], ldB + sOff + nt4 * 2048 + ko[0]);
        #pragma unroll
        for (int mt = 0; mt < 2; mt++)
            ldsm_x4(afr[0][mt], ldA + sOff + mt * 2048 + ko[0]);

        #pragma unroll
        for (int ks = 0; ks < 4; ks++) {
            int cur = ks & 1;
            int nxt = cur ^ 1;
            if (ks < 3) {
                #pragma unroll
                for (int nt4 = 0; nt4 < 4; nt4++)
                    ldsm_x4(bfr[nxt][nt4], ldB + sOff + nt4 * 2048 + ko[ks + 1]);
                #pragma unroll
                for (int mt = 0; mt < 2; mt++)
                    ldsm_x4(afr[nxt][mt], ldA + sOff + mt * 2048 + ko[ks + 1]);
            }
            #pragma unroll
            for (int mt = 0; mt < 2; mt++) {
                #pragma unroll
                for (int nt4 = 0; nt4 < 4; nt4++) {
                    mma_bf16(acc[mt][nt4 * 2 + 0], afr[cur][mt], bfr[cur][nt4][0], bfr[cur][nt4][2]);
                    mma_bf16(acc[mt][nt4 * 2 + 1], afr[cur][mt], bfr[cur][nt4][1], bfr[cur][nt4][3]);
                }
            }
        }
    }

    // ---------------- epilogue: branch-free partial LSE (target included) ----------------
    float* rsum = (float*)(SA + SM_RSUM);
    int g = lid >> 2;
    int tg = lid & 3;

    float rs[4] = {0.f, 0.f, 0.f, 0.f};
    #pragma unroll
    for (int mt = 0; mt < 2; mt++) {
        int rlo = warpM * 32 + mt * 16 + g;
        int rhi = rlo + 8;
        int tlo = tgt_s[rlo];
        int thi = tgt_s[rhi];
        #pragma unroll
        for (int nt = 0; nt < 8; nt++) {
            int colb = warpN * 64 + nt * 8 + tg * 2;
            #pragma unroll
            for (int q = 0; q < 4; q++) {
                int cls = cls0 + colb + (q & 1);
                float cosv = acc[mt][nt][q];
                int t = (q < 2) ? tlo : thi;
                if (cls == t) g_cost[b0 + ((q < 2) ? rlo : rhi)] = cosv;
                rs[mt * 2 + (q >> 1)] += ex2_approx(fmaf(EXPK, cosv, -EXPK));
            }
        }
    }
    #pragma unroll
    for (int i = 0; i < 4; i++) {
        rs[i] += __shfl_xor_sync(0xffffffffu, rs[i], 1);
        rs[i] += __shfl_xor_sync(0xffffffffu, rs[i], 2);
    }
    if (tg == 0) {
        #pragma unroll
        for (int mt = 0; mt < 2; mt++) {
            int rlo = warpM * 32 + mt * 16 + g;
            rsum[rlo * 2 + warpN] = rs[mt * 2 + 0];
            rsum[(rlo + 8) * 2 + warpN] = rs[mt * 2 + 1];
        }
    }
    __syncthreads();
    if (tid < 128) {
        g_partials[(size_t)(b0 + tid) * PPAD + ctile] = rsum[tid * 2] + rsum[tid * 2 + 1];
    }
}

// ======================= K3: reduce + margin + final mean (fused) =======================
// 64 blocks x 8 warps, warp per batch row. Subtracts the bit-identical target
// term that the gemm epilogue summed, then adds the phi term.
__global__ void __launch_bounds__(256) k_reduce_b(float* __restrict__ out) {
    __shared__ unsigned last;
    int tid = threadIdx.x;
    int wid = tid >> 5;
    int lane = tid & 31;
    int b = blockIdx.x * 8 + wid;

    float acc = 0.0f;
    for (int i = lane; i < NCTA; i += 32)
        acc += g_partials[(size_t)b * PPAD + i];
    #pragma unroll
    for (int m = 16; m >= 1; m >>= 1) acc += __shfl_xor_sync(0xffffffffu, acc, m);
    if (lane == 0) {
        float ct = g_cost[b];
        acc -= ex2_approx(fmaf(EXPK, ct, -EXPK));   // bit-identical to gemm's added term
        float st = sqrtf(fmaxf(1.0f - ct * ct, 0.0f));
        float phi = ct * C_COS_M - st * C_SIN_M;
        phi = (ct > C_TH) ? phi : (ct - C_MM);
        acc += ex2_approx(fmaf(EXPK, phi, -EXPK));
        g_lossb[b] = 64.0f + logf(acc) - 64.0f * phi;
    }
    __threadfence();
    __syncthreads();                  // all 8 rows of this block written + fenced
    if (tid == 0) last = atomicAdd(&g_ctr, 1u);
    __syncthreads();
    if (last == 63u) {                // final block: mean over 512 (fixed order)
        __shared__ float red[8];
        float v = g_lossb[tid] + g_lossb[tid + 256];
        #pragma unroll
        for (int m = 16; m >= 1; m >>= 1) v += __shfl_xor_sync(0xffffffffu, v, m);
        if (lane == 0) red[wid] = v;
        __syncthreads();
        if (tid == 0) {
            float s = 0.0f;
            #pragma unroll
            for (int i = 0; i < 8; i++) s += red[i];
            out[0] = s * (1.0f / (float)BATCHN);
        }
    }
}

// ======================= launch =======================
extern "C" void kernel_launch(void* const* d_in, const int* in_sizes, int n_in,
                              void* d_out, int out_size) {
    const float* x = (const float*)d_in[0];
    const float* w = (const float*)d_in[1];
    const int* tgt_raw = (const int*)d_in[2];
    float* out = (float*)d_out;

    cudaFuncSetAttribute(k_gemm, cudaFuncAttributeMaxDynamicSharedMemorySize, SMEM_DYN);

    k_norm_all<<<(CPAD + BATCHN) / 4, 128>>>(w, x, tgt_raw);
    k_gemm<<<NCTA * 4, 256, SMEM_DYN>>>();
    k_reduce_b<<<64, 256>>>(out);
}